// round 16
// baseline (speedup 1.0000x reference)
#include <cuda_runtime.h>
#include <cuda_bf16.h>
#include <cstdint>
#include <math.h>

#define BB   4
#define NBLK 256
#define LL   64
#define KK   65
#define CCH  512
#define HH   8
#define SCALE 0.125f

// ---------------- scratch (device globals; 16B aligned) ----------------
__device__ __align__(16) float g_qkv[(size_t)BB * NBLK * KK * 3 * CCH];      // 409 MB
__device__ __align__(16) __nv_bfloat16 g_akvh[(size_t)BB * NBLK * KK * CCH]; // 68 MB
__device__ __align__(16) __nv_bfloat16 g_akvl[(size_t)BB * NBLK * KK * CCH];
__device__ __align__(16) __nv_bfloat16 g_aoh[(size_t)BB * NBLK * LL * CCH];  // 67 MB
__device__ __align__(16) __nv_bfloat16 g_aol[(size_t)BB * NBLK * LL * CCH];
__device__ __align__(16) __nv_bfloat16 g_wqkvTh[3 * CCH * CCH];              // [1536][512]
__device__ __align__(16) __nv_bfloat16 g_wqkvTl[3 * CCH * CCH];
__device__ __align__(16) __nv_bfloat16 g_wprojTh[CCH * CCH];                 // [512][512]
__device__ __align__(16) __nv_bfloat16 g_wprojTl[CCH * CCH];

// ---------------- helpers (sm_80-era instructions only: compile-safe) -------
__device__ __forceinline__ uint32_t smem_u32(const void* p) {
    uint32_t a;
    asm("{ .reg .u64 t; cvta.to.shared.u64 t, %1; cvt.u32.u64 %0, t; }" : "=r"(a) : "l"(p));
    return a;
}
__device__ __forceinline__ void cp16(uint32_t s, const void* g) {
    asm volatile("cp.async.cg.shared.global [%0], [%1], 16;" :: "r"(s), "l"(g));
}
__device__ __forceinline__ void ldsm4(uint32_t* r, uint32_t a) {
    asm volatile("ldmatrix.sync.aligned.m8n8.x4.shared.b16 {%0,%1,%2,%3}, [%4];"
        : "=r"(r[0]), "=r"(r[1]), "=r"(r[2]), "=r"(r[3]) : "r"(a));
}
__device__ __forceinline__ void mma16816(float* d, const uint32_t* a, const uint32_t* b) {
    asm volatile("mma.sync.aligned.m16n8k16.row.col.f32.bf16.bf16.f32 "
        "{%0,%1,%2,%3}, {%4,%5,%6,%7}, {%8,%9}, {%0,%1,%2,%3};"
        : "+f"(d[0]), "+f"(d[1]), "+f"(d[2]), "+f"(d[3])
        : "r"(a[0]), "r"(a[1]), "r"(a[2]), "r"(a[3]), "r"(b[0]), "r"(b[1]));
}

// ---------------- 1) fused mean + kv split: one CTA per (b,nb) block ---------
__global__ void kvprep2(const float* __restrict__ x) {
    int blk = blockIdx.x;                   // 0..1023
    int t = threadIdx.x;                    // 0..255
    const float* xb = x + (size_t)blk * LL * CCH + t * 2;
    size_t obase = (size_t)blk * KK * CCH + t * 2;
    float m0 = 0.f, m1 = 0.f;
#pragma unroll 4
    for (int r = 0; r < LL; r++) {
        float2 v = *(const float2*)(xb + (size_t)r * CCH);
        m0 += v.x; m1 += v.y;
        __nv_bfloat16 h0 = __float2bfloat16_rn(v.x);
        __nv_bfloat16 h1 = __float2bfloat16_rn(v.y);
        *(__nv_bfloat162*)(g_akvh + obase + (size_t)r * CCH) = __nv_bfloat162{h0, h1};
        *(__nv_bfloat162*)(g_akvl + obase + (size_t)r * CCH) =
            __nv_bfloat162{__float2bfloat16_rn(v.x - __bfloat162float(h0)),
                           __float2bfloat16_rn(v.y - __bfloat162float(h1))};
    }
    m0 *= (1.0f / LL); m1 *= (1.0f / LL);
    __nv_bfloat16 h0 = __float2bfloat16_rn(m0);
    __nv_bfloat16 h1 = __float2bfloat16_rn(m1);
    *(__nv_bfloat162*)(g_akvh + obase + (size_t)LL * CCH) = __nv_bfloat162{h0, h1};
    *(__nv_bfloat162*)(g_akvl + obase + (size_t)LL * CCH) =
        __nv_bfloat162{__float2bfloat16_rn(m0 - __bfloat162float(h0)),
                       __float2bfloat16_rn(m1 - __bfloat162float(h1))};
}

// ---------------- 2) weight transpose + split: w[512][N] -> wT[N][512] hi/lo ----
__global__ void wprep(const float* __restrict__ w, __nv_bfloat16* __restrict__ oh,
                      __nv_bfloat16* __restrict__ ol, int N) {
    __shared__ float t[32][33];
    int n0 = blockIdx.x * 32, k0 = blockIdx.y * 32;
    int tx = threadIdx.x, ty = threadIdx.y;     // (32, 8)
#pragma unroll
    for (int j = 0; j < 4; j++)
        t[ty * 4 + j][tx] = w[(size_t)(k0 + ty * 4 + j) * N + n0 + tx];
    __syncthreads();
#pragma unroll
    for (int j = 0; j < 4; j++) {
        float v = t[tx][ty * 4 + j];
        __nv_bfloat16 hi = __float2bfloat16_rn(v);
        __nv_bfloat16 lo = __float2bfloat16_rn(v - __bfloat162float(hi));
        size_t idx = (size_t)(n0 + ty * 4 + j) * CCH + k0 + tx;
        oh[idx] = hi; ol[idx] = lo;
    }
}

// ---------------- 3) split-bf16 3-pass GEMM via mma.sync ---------------------
// C[M][NT] = A[M][512] @ W[NT][512]^T + bias.
// CTA tile 128(M) x 256(N), 512 threads = 16 warps (4M x 4N), warp tile 32x64.
// K-chunk 32, 4-stage cp.async pipeline (loads run up to 3 chunks ahead).
// Stage (48 KB): Ah @0 (8K), Al @8K, Bh @16K (16K), Bl @32K. 64B rows, XOR swizzle
// (chunk ^= row & 3).
#define GSTAGE (48 * 1024)
#define GEMM_SMEM (4 * GSTAGE)
#define NCHUNK 16

template <int NT>
__global__ __launch_bounds__(512)
void gemm_mma3(const __nv_bfloat16* __restrict__ Ah, const __nv_bfloat16* __restrict__ Al,
               const __nv_bfloat16* __restrict__ Wh, const __nv_bfloat16* __restrict__ Wl,
               const float* __restrict__ bias, float* __restrict__ C) {
    extern __shared__ __align__(16) char smem[];
    uint32_t sb = smem_u32(smem);
    int tid = threadIdx.x, lane = tid & 31, wid = tid >> 5;
    int g = lane >> 2, t4 = lane & 3;
    int wm = (wid >> 2) * 32;            // 4 M-warps
    int wn = (wid & 3) * 64;             // 4 N-warps
    size_t m0 = (size_t)blockIdx.y * 128;
    int n0 = blockIdx.x * 256;

    float acc[2][8][4];
#pragma unroll
    for (int i = 0; i < 2; i++)
#pragma unroll
        for (int j = 0; j < 8; j++)
#pragma unroll
            for (int q = 0; q < 4; q++) acc[i][j][q] = 0.f;

    // ldmatrix lane addressing
    int lt = lane >> 3, lr = lane & 7;
    int amrow[2];
#pragma unroll
    for (int mi = 0; mi < 2; mi++) amrow[mi] = wm + mi * 16 + ((lt & 1) << 3) + lr;
    int a_chadd = lt >> 1;
    int bnrow[4];
#pragma unroll
    for (int bb = 0; bb < 4; bb++) bnrow[bb] = wn + bb * 16 + ((lt >> 1) << 3) + lr;
    int b_chadd = lt & 1;

    // Per-stage loads: A hi/lo 512 lines each (1/thr), B hi/lo 1024 each (2/thr)
    int arow_ = tid >> 2, ach_ = tid & 3;
    uint32_t aso_ = (uint32_t)(arow_ * 64 + ((ach_ ^ (arow_ & 3)) << 4));
    size_t agp_ = (m0 + arow_) * CCH + ach_ * 8;

#define LOAD_STAGE(stg, ko)                                                        \
    {                                                                              \
        uint32_t st_ = sb + (uint32_t)(stg) * GSTAGE;                              \
        cp16(st_ + aso_,        Ah + agp_ + (ko));                                 \
        cp16(st_ + 8192 + aso_, Al + agp_ + (ko));                                 \
        _Pragma("unroll")                                                          \
        for (int i_ = 0; i_ < 2; i_++) {                                           \
            int l_ = tid + i_ * 512;                                               \
            int row_ = l_ >> 2, ch_ = l_ & 3;                                      \
            uint32_t so_ = (uint32_t)(row_ * 64 + ((ch_ ^ (row_ & 3)) << 4));      \
            size_t gb_ = (size_t)(n0 + row_) * CCH + (ko) + ch_ * 8;               \
            cp16(st_ + 16384 + so_, Wh + gb_);                                     \
            cp16(st_ + 32768 + so_, Wl + gb_);                                     \
        }                                                                          \
        asm volatile("cp.async.commit_group;" ::: "memory");                       \
    }

    LOAD_STAGE(0, 0);
    LOAD_STAGE(1, 32);
    LOAD_STAGE(2, 64);

    for (int c = 0; c < NCHUNK; c++) {
        // stage c complete when at most (NCHUNK-1-c) newer groups remain, capped at 2
        if (c <= NCHUNK - 3)      asm volatile("cp.async.wait_group 2;" ::: "memory");
        else if (c == NCHUNK - 2) asm volatile("cp.async.wait_group 1;" ::: "memory");
        else                      asm volatile("cp.async.wait_group 0;" ::: "memory");
        __syncthreads();
        if (c < NCHUNK - 3) LOAD_STAGE((c + 3) & 3, (c + 3) * 32);

        uint32_t st = sb + (uint32_t)(c & 3) * GSTAGE;
#pragma unroll
        for (int ks = 0; ks < 2; ks++) {
            int cb = ks * 2;
            uint32_t ah[2][4], al[2][4], bfr[8][2];
#pragma unroll
            for (int mi = 0; mi < 2; mi++) {
                int r = amrow[mi];
                uint32_t ad = st + r * 64 + (((cb + a_chadd) ^ (r & 3)) << 4);
                ldsm4(ah[mi], ad);
                ldsm4(al[mi], ad + 8192);
            }
            // phase 1: B-hi -> AhBh + AlBh
#pragma unroll
            for (int bb = 0; bb < 4; bb++) {
                int r = bnrow[bb];
                uint32_t bd = st + 16384 + r * 64 + (((cb + b_chadd) ^ (r & 3)) << 4);
                uint32_t rr[4];
                ldsm4(rr, bd);
                bfr[2 * bb][0] = rr[0]; bfr[2 * bb][1] = rr[1];
                bfr[2 * bb + 1][0] = rr[2]; bfr[2 * bb + 1][1] = rr[3];
            }
#pragma unroll
            for (int mi = 0; mi < 2; mi++)
#pragma unroll
                for (int ni = 0; ni < 8; ni++) {
                    mma16816(acc[mi][ni], ah[mi], bfr[ni]);
                    mma16816(acc[mi][ni], al[mi], bfr[ni]);
                }
            // phase 2: B-lo -> AhBl (reuse bfr)
#pragma unroll
            for (int bb = 0; bb < 4; bb++) {
                int r = bnrow[bb];
                uint32_t bd = st + 32768 + r * 64 + (((cb + b_chadd) ^ (r & 3)) << 4);
                uint32_t rr[4];
                ldsm4(rr, bd);
                bfr[2 * bb][0] = rr[0]; bfr[2 * bb][1] = rr[1];
                bfr[2 * bb + 1][0] = rr[2]; bfr[2 * bb + 1][1] = rr[3];
            }
#pragma unroll
            for (int mi = 0; mi < 2; mi++)
#pragma unroll
                for (int ni = 0; ni < 8; ni++)
                    mma16816(acc[mi][ni], ah[mi], bfr[ni]);
        }
    }

    // epilogue: bias + fp32 store
#pragma unroll
    for (int ni = 0; ni < 8; ni++) {
        int col = n0 + wn + ni * 8 + t4 * 2;
        float b0 = bias[col], b1 = bias[col + 1];
#pragma unroll
        for (int mi = 0; mi < 2; mi++) {
            size_t r0 = m0 + wm + mi * 16 + g;
            float2 v0 = make_float2(acc[mi][ni][0] + b0, acc[mi][ni][1] + b1);
            float2 v1 = make_float2(acc[mi][ni][2] + b0, acc[mi][ni][3] + b1);
            *(float2*)(C + r0 * NT + col)       = v0;
            *(float2*)(C + (r0 + 8) * NT + col) = v1;
        }
    }
}

// ---------------- 4) attention (fp32; emits bf16 hi/lo for proj) -------------
// K tile stored at stride 68 floats: lane-stride 68 words == 4 mod 32 -> LDS.128
// across a warp covers all 32 banks conflict-free; enables float4 QK inner loop.
#define KS_STRIDE 68
#define KS_FLOATS (65 * KS_STRIDE)          // 4420, mult of 4
#define ATTN_SMEM_FLOATS (64 * 64 + KS_FLOATS + 65 * 64 + 64 * 66)

__global__ void attn_kernel(const int* __restrict__ mask,
                            const float* __restrict__ ef) {
    extern __shared__ float sm[];
    float* qs = sm;                       // 64 x 64
    float* ks = qs + 64 * 64;             // 65 x 64, stride 68
    float* vs = ks + KS_FLOATS;           // 65 x 64 (16B-aligned: 8516*4 % 16 == 0)
    float* ps = vs + 65 * 64;             // 64 x 66

    int bh  = blockIdx.x;
    int hd  = bh & (HH - 1);
    int blk = bh >> 3;
    int nb  = blk & (NBLK - 1);
    int tid = threadIdx.x;
    int w   = tid >> 5;
    int lane = tid & 31;

    const float* qbase = g_qkv + (size_t)blk * 65 * 1536 + hd * 64;
    const float* kbase = qbase + 512;
    const float* vbase = qbase + 1024;

    for (int idx = tid; idx < 64 * 16; idx += 256) {
        int r = idx >> 4, c4 = (idx & 15) << 2;
        *(float4*)(qs + r * 64 + c4) = *(const float4*)(qbase + (size_t)r * 1536 + c4);
    }
    for (int idx = tid; idx < 65 * 16; idx += 256) {
        int r = idx >> 4, c4 = (idx & 15) << 2;
        float4 v = *(const float4*)(kbase + (size_t)r * 1536 + c4);
        *(float4*)(ks + r * KS_STRIDE + c4) = v;
    }
    for (int idx = tid; idx < 65 * 16; idx += 256) {
        int r = idx >> 4, c4 = (idx & 15) << 2;
        *(float4*)(vs + r * 64 + c4) = *(const float4*)(vbase + (size_t)r * 1536 + c4);
    }
    __syncthreads();

    int j0 = lane, j1 = lane + 32;
    float acc0[8], acc1[8];
#pragma unroll
    for (int r = 0; r < 8; r++) { acc0[r] = 0.f; acc1[r] = 0.f; }

    // j=64 (block-node) column: shuffle-reduced dot, once per row
    float s2v[8];
    {
        float k64a = ks[64 * KS_STRIDE + lane];
        float k64b = ks[64 * KS_STRIDE + lane + 32];
#pragma unroll
        for (int r = 0; r < 8; r++) {
            int i = w * 8 + r;
            float part = qs[i * 64 + lane] * k64a + qs[i * 64 + lane + 32] * k64b;
#pragma unroll
            for (int o = 16; o > 0; o >>= 1) part += __shfl_xor_sync(0xffffffffu, part, o);
            s2v[r] = fmaf(part, SCALE, 1.0f);   // mask forced true, bias 1
        }
    }

    // vectorized QK: float4 over k-dim
    const float* k0p = ks + j0 * KS_STRIDE;
    const float* k1p = ks + j1 * KS_STRIDE;
#pragma unroll
    for (int k4 = 0; k4 < 16; k4++) {
        float4 kv0 = *(const float4*)(k0p + k4 * 4);
        float4 kv1 = *(const float4*)(k1p + k4 * 4);
#pragma unroll
        for (int r = 0; r < 8; r++) {
            float4 qv = *(const float4*)(qs + (w * 8 + r) * 64 + k4 * 4);
            acc0[r] = fmaf(qv.x, kv0.x, fmaf(qv.y, kv0.y,
                      fmaf(qv.z, kv0.z, fmaf(qv.w, kv0.w, acc0[r]))));
            acc1[r] = fmaf(qv.x, kv1.x, fmaf(qv.y, kv1.y,
                      fmaf(qv.z, kv1.z, fmaf(qv.w, kv1.w, acc1[r]))));
        }
    }

#pragma unroll
    for (int r = 0; r < 8; r++) {
        int i = w * 8 + r;
        size_t mbase = ((size_t)nb * 64 + i) * 65;
        float b0 = (j0 == i) ? 1.0f : ef[(mbase + j0) * 4 + 3];
        float b1 = (j1 == i) ? 1.0f : ef[(mbase + j1) * 4 + 3];
        float s0 = (mask[mbase + j0] != 0) ? fmaf(acc0[r], SCALE, b0) : -1e9f;
        float s1 = (mask[mbase + j1] != 0) ? fmaf(acc1[r], SCALE, b1) : -1e9f;
        float s2 = s2v[r];

        float m = fmaxf(fmaxf(s0, s1), s2);
#pragma unroll
        for (int o = 16; o > 0; o >>= 1) m = fmaxf(m, __shfl_xor_sync(0xffffffffu, m, o));
        float e0 = __expf(s0 - m), e1 = __expf(s1 - m), e2 = __expf(s2 - m);
        float sum = e0 + e1;
#pragma unroll
        for (int o = 16; o > 0; o >>= 1) sum += __shfl_xor_sync(0xffffffffu, sum, o);
        sum += e2;
        float inv = 1.0f / sum;
        float* prow = ps + i * 66;
        prow[j0] = e0 * inv;
        prow[j1] = e1 * inv;
        if (lane == 0) prow[64] = e2 * inv;
    }
    __syncwarp();

    float o0[8], o1[8];
#pragma unroll
    for (int r = 0; r < 8; r++) { o0[r] = 0.f; o1[r] = 0.f; }
    for (int j = 0; j < 65; j++) {
        float v0 = vs[j * 64 + lane];
        float v1 = vs[j * 64 + lane + 32];
#pragma unroll
        for (int r = 0; r < 8; r++) {
            float p = ps[(w * 8 + r) * 66 + j];
            o0[r] = fmaf(p, v0, o0[r]);
            o1[r] = fmaf(p, v1, o1[r]);
        }
    }
#pragma unroll
    for (int r = 0; r < 8; r++) {
        size_t orow = (size_t)blk * 64 + (w * 8 + r);
        size_t c0 = orow * 512 + hd * 64 + lane;
        float va = o0[r], vb = o1[r];
        __nv_bfloat16 ha = __float2bfloat16_rn(va);
        __nv_bfloat16 hb = __float2bfloat16_rn(vb);
        g_aoh[c0]      = ha;
        g_aoh[c0 + 32] = hb;
        g_aol[c0]      = __float2bfloat16_rn(va - __bfloat162float(ha));
        g_aol[c0 + 32] = __float2bfloat16_rn(vb - __bfloat162float(hb));
    }
}

// ---------------------------------------------------------------------------
extern "C" void kernel_launch(void* const* d_in, const int* in_sizes, int n_in,
                              void* d_out, int out_size) {
    const float* x      = (const float*)d_in[0];
    const int*   mask   = (const int*)d_in[1];
    const float* ef     = (const float*)d_in[2];
    const float* qkv_w  = (const float*)d_in[3];
    const float* qkv_b  = (const float*)d_in[4];
    const float* proj_w = (const float*)d_in[5];
    const float* proj_b = (const float*)d_in[6];
    float*       out    = (float*)d_out;
    (void)in_sizes; (void)n_in; (void)out_size;

    const int ATTN_SMEM = ATTN_SMEM_FLOATS * 4;
    cudaFuncSetAttribute(attn_kernel, cudaFuncAttributeMaxDynamicSharedMemorySize, ATTN_SMEM);
    cudaFuncSetAttribute(gemm_mma3<1536>, cudaFuncAttributeMaxDynamicSharedMemorySize, GEMM_SMEM);
    cudaFuncSetAttribute(gemm_mma3<512>,  cudaFuncAttributeMaxDynamicSharedMemorySize, GEMM_SMEM);

    __nv_bfloat16 *akvh, *akvl, *aoh, *aol, *wqh, *wql, *wph, *wpl;
    cudaGetSymbolAddress((void**)&akvh, g_akvh);
    cudaGetSymbolAddress((void**)&akvl, g_akvl);
    cudaGetSymbolAddress((void**)&aoh,  g_aoh);
    cudaGetSymbolAddress((void**)&aol,  g_aol);
    cudaGetSymbolAddress((void**)&wqh,  g_wqkvTh);
    cudaGetSymbolAddress((void**)&wql,  g_wqkvTl);
    cudaGetSymbolAddress((void**)&wph,  g_wprojTh);
    cudaGetSymbolAddress((void**)&wpl,  g_wprojTl);
    float* qkv;
    cudaGetSymbolAddress((void**)&qkv, g_qkv);

    kvprep2<<<BB * NBLK, 256>>>(x);
    wprep<<<dim3(48, 16), dim3(32, 8)>>>(qkv_w, wqh, wql, 1536);
    wprep<<<dim3(16, 16), dim3(32, 8)>>>(proj_w, wph, wpl, 512);
    // QKV: M = 66560 = 520*128, N = 1536 = 6*256
    gemm_mma3<1536><<<dim3(6, 520), 512, GEMM_SMEM>>>(akvh, akvl, wqh, wql, qkv_b, qkv);
    attn_kernel<<<BB * NBLK * HH, 256, ATTN_SMEM>>>(mask, ef);
    // proj: M = 65536 = 512*128, N = 512 = 2*256
    gemm_mma3<512><<<dim3(2, 512), 512, GEMM_SMEM>>>(aoh, aol, wph, wpl, proj_b, out);
}